// round 1
// baseline (speedup 1.0000x reference)
#include <cuda_runtime.h>
#include <cuda_bf16.h>

// ---------------------------------------------------------------------------
// ParamMakeFeature: fold rotation into MLP weights, then run a packed-f32x2
// 3->15->15->15 MLP per point.
//
// Inputs (metadata order):
//  0: x      [B,3,N]   float32
//  1: randRm [B,3,3]   float32
//  2: W1 [15,3]  3: b1[15]  4: W2[15,15]  5: b2[15]  6: W3[15,15]  7: b3[15]
//  8: Q1 [3,3]   9: Q2[5,9]  10: Q3[7,27]
// Output: [B,15,N] float32
// ---------------------------------------------------------------------------

typedef unsigned long long u64;

#define FEAT 15
#define MAXB 32

// per-batch packed params layout (units: u64 = duplicated f32x2 pair)
#define OFF_W1R 0     // 45:  [f*3+j]
#define OFF_B1  45    // 15
#define OFF_W2  60    // 240: [g*16+f], f<15 valid
#define OFF_B2  300   // 15 (+1 pad)
#define OFF_M3  316   // 240: [p*16+f]
#define OFF_C3  556   // 15 (+1 pad)
#define PAR_STRIDE 572

__device__ u64 g_params[MAXB * PAR_STRIDE];

__device__ __forceinline__ u64 pk2(float lo, float hi) {
    u64 r; asm("mov.b64 %0, {%1,%2};" : "=l"(r) : "f"(lo), "f"(hi)); return r;
}
__device__ __forceinline__ void upk2(u64 v, float& lo, float& hi) {
    asm("mov.b64 {%0,%1}, %2;" : "=f"(lo), "=f"(hi) : "l"(v));
}
__device__ __forceinline__ u64 ffma2(u64 a, u64 b, u64 c) {
    u64 d; asm("fma.rn.f32x2 %0, %1, %2, %3;" : "=l"(d) : "l"(a), "l"(b), "l"(c));
    return d;
}
__device__ __forceinline__ u64 relu2(u64 v) {
    float lo, hi; upk2(v, lo, hi);
    lo = fmaxf(lo, 0.f); hi = fmaxf(hi, 0.f);
    return pk2(lo, hi);
}

// ---------------------------------------------------------------------------
// Precompute kernel: one block per batch. Builds W1R, D-blocks, M3 = Dblk*W3,
// c3 = Dblk*b3, and writes everything duplicated as f32x2 pairs.
// ---------------------------------------------------------------------------
__global__ void precompute_kernel(
    const float* __restrict__ R_all,
    const float* __restrict__ W1, const float* __restrict__ b1,
    const float* __restrict__ W2, const float* __restrict__ b2,
    const float* __restrict__ W3, const float* __restrict__ b3,
    const float* __restrict__ Q1, const float* __restrict__ Q2,
    const float* __restrict__ Q3)
{
    const int b = blockIdx.x;
    const int tid = threadIdx.x;

    __shared__ float R[9];
    __shared__ float K2[81];
    __shared__ float K3[729];
    __shared__ float E2[9][5];
    __shared__ float E3[27][7];
    __shared__ float D1[3][3], D2[5][5], D3[7][7];
    __shared__ float M3[15][15], c3[15], W1Rs[15][3];

    // phase A: load R
    if (tid < 9) R[tid] = R_all[b * 9 + tid];
    __syncthreads();

    // phase B: K2 (R kron R), D1 = Q1 R Q1^T, W1R = W1 * R^T
    if (tid < 81) {
        int row = tid / 9, col = tid % 9;
        int i = row / 3, k = row % 3, j = col / 3, l = col % 3;
        K2[tid] = R[i * 3 + j] * R[k * 3 + l];
    } else if (tid >= 96 && tid < 105) {
        int t = tid - 96, p = t / 3, q = t % 3;
        float s = 0.f;
        for (int i = 0; i < 3; i++)
            for (int j = 0; j < 3; j++)
                s += Q1[p * 3 + i] * R[i * 3 + j] * Q1[q * 3 + j];
        D1[p][q] = s;
    } else if (tid >= 112 && tid < 157) {
        int t = tid - 112, f = t / 3, j = t % 3;
        float s = 0.f;
        for (int i = 0; i < 3; i++) s += W1[f * 3 + i] * R[j * 3 + i];
        W1Rs[f][j] = s;
    }
    __syncthreads();

    // phase C: E2 = K2 * Q2^T ; K3 = kron(K2, R)
    if (tid < 45) {
        int i = tid / 5, q = tid % 5;
        float s = 0.f;
        for (int j = 0; j < 9; j++) s += K2[i * 9 + j] * Q2[q * 9 + j];
        E2[i][q] = s;
    }
    for (int idx = tid; idx < 729; idx += blockDim.x) {
        int row = idx / 27, col = idx % 27;
        int a = row / 3, m = row % 3, bb = col / 3, nn = col % 3;
        K3[idx] = K2[a * 9 + bb] * R[m * 3 + nn];
    }
    __syncthreads();

    // phase D: D2 = Q2 * E2 ; E3 = K3 * Q3^T
    if (tid < 25) {
        int p = tid / 5, q = tid % 5;
        float s = 0.f;
        for (int i = 0; i < 9; i++) s += Q2[p * 9 + i] * E2[i][q];
        D2[p][q] = s;
    } else if (tid >= 32 && tid < 32 + 189) {
        int t = tid - 32, u = t / 7, q = t % 7;
        float s = 0.f;
        for (int v = 0; v < 27; v++) s += K3[u * 27 + v] * Q3[q * 27 + v];
        E3[u][q] = s;
    }
    __syncthreads();

    // phase E: D3 = Q3 * E3
    if (tid < 49) {
        int p = tid / 7, q = tid % 7;
        float s = 0.f;
        for (int u = 0; u < 27; u++) s += Q3[p * 27 + u] * E3[u][q];
        D3[p][q] = s;
    }
    __syncthreads();

    // phase F: M3 = blockdiag(D1,D2,D3) * W3 ; c3 = blockdiag * b3
    if (tid < 225) {
        int p = tid / 15, f = tid % 15;
        float s = 0.f;
        if (p < 3)       { for (int q = 0; q < 3; q++) s += D1[p][q]     * W3[q * 15 + f]; }
        else if (p < 8)  { for (int q = 0; q < 5; q++) s += D2[p - 3][q] * W3[(3 + q) * 15 + f]; }
        else             { for (int q = 0; q < 7; q++) s += D3[p - 8][q] * W3[(8 + q) * 15 + f]; }
        M3[p][f] = s;
    } else if (tid < 240) {
        int p = tid - 225;
        float s = 0.f;
        if (p < 3)       { for (int q = 0; q < 3; q++) s += D1[p][q]     * b3[q]; }
        else if (p < 8)  { for (int q = 0; q < 5; q++) s += D2[p - 3][q] * b3[3 + q]; }
        else             { for (int q = 0; q < 7; q++) s += D3[p - 8][q] * b3[8 + q]; }
        c3[p] = s;
    }
    __syncthreads();

    // phase G: write duplicated-pair params
    u64* dst = g_params + (size_t)b * PAR_STRIDE;
    for (int idx = tid; idx < PAR_STRIDE; idx += blockDim.x) {
        float v = 0.f;
        if (idx < 45) {
            v = W1Rs[idx / 3][idx % 3];
        } else if (idx < 60) {
            v = b1[idx - 45];
        } else if (idx < 300) {
            int r = idx - 60, g = r / 16, f = r % 16;
            v = (f < 15) ? W2[g * 15 + f] : 0.f;
        } else if (idx < 316) {
            v = (idx < 315) ? b2[idx - 300] : 0.f;
        } else if (idx < 556) {
            int r = idx - 316, p = r / 16, f = r % 16;
            v = (f < 15) ? M3[p][f] : 0.f;
        } else {
            v = (idx < 571) ? c3[idx - 556] : 0.f;
        }
        dst[idx] = pk2(v, v);
    }
}

// ---------------------------------------------------------------------------
// Main kernel: each thread handles pairs of adjacent points with packed f32x2.
// ---------------------------------------------------------------------------
#define THREADS 256
#define ITERS 4

__global__ __launch_bounds__(THREADS)
void mf_main_kernel(const float* __restrict__ x, float* __restrict__ out,
                    int N, int pairs)
{
    const int b = blockIdx.y;
    __shared__ u64 sw[PAR_STRIDE];
    {
        const u64* src = g_params + (size_t)b * PAR_STRIDE;
        for (int i = threadIdx.x; i < PAR_STRIDE; i += THREADS) sw[i] = src[i];
    }
    __syncthreads();

    const float2* __restrict__ x0 = (const float2*)(x + (size_t)(b * 3 + 0) * N);
    const float2* __restrict__ x1 = (const float2*)(x + (size_t)(b * 3 + 1) * N);
    const float2* __restrict__ x2 = (const float2*)(x + (size_t)(b * 3 + 2) * N);
    float* __restrict__ ob = out + (size_t)b * FEAT * N;

#pragma unroll 1
    for (int it = 0; it < ITERS; ++it) {
        int p = blockIdx.x * (THREADS * ITERS) + it * THREADS + threadIdx.x;
        if (p >= pairs) break;

        float2 a0 = x0[p], a1 = x1[p], a2 = x2[p];
        u64 xv0 = pk2(a0.x, a0.y);
        u64 xv1 = pk2(a1.x, a1.y);
        u64 xv2 = pk2(a2.x, a2.y);

        // stage 1: h1 = relu(W1R * x + b1)
        u64 h1[FEAT];
#pragma unroll
        for (int f = 0; f < FEAT; f++) {
            u64 acc = sw[OFF_B1 + f];
            acc = ffma2(xv0, sw[OFF_W1R + f * 3 + 0], acc);
            acc = ffma2(xv1, sw[OFF_W1R + f * 3 + 1], acc);
            acc = ffma2(xv2, sw[OFF_W1R + f * 3 + 2], acc);
            h1[f] = relu2(acc);
        }

        // stage 2: h2 = relu(W2 * h1 + b2)
        u64 h2[FEAT];
#pragma unroll
        for (int g = 0; g < FEAT; g++) {
            u64 acc = sw[OFF_B2 + g];
#pragma unroll
            for (int f = 0; f < FEAT; f++)
                acc = ffma2(h1[f], sw[OFF_W2 + g * 16 + f], acc);
            h2[g] = relu2(acc);
        }

        // stage 3: y = M3 * h2 + c3, store
#pragma unroll
        for (int pp = 0; pp < FEAT; pp++) {
            u64 acc = sw[OFF_C3 + pp];
#pragma unroll
            for (int f = 0; f < FEAT; f++)
                acc = ffma2(h2[f], sw[OFF_M3 + pp * 16 + f], acc);
            float lo, hi; upk2(acc, lo, hi);
            ((float2*)(ob + (size_t)pp * N))[p] = make_float2(lo, hi);
        }
    }
}

// ---------------------------------------------------------------------------
extern "C" void kernel_launch(void* const* d_in, const int* in_sizes, int n_in,
                              void* d_out, int out_size)
{
    const float* x  = (const float*)d_in[0];
    const float* R  = (const float*)d_in[1];
    const float* W1 = (const float*)d_in[2];
    const float* b1 = (const float*)d_in[3];
    const float* W2 = (const float*)d_in[4];
    const float* b2 = (const float*)d_in[5];
    const float* W3 = (const float*)d_in[6];
    const float* b3 = (const float*)d_in[7];
    const float* Q1 = (const float*)d_in[8];
    const float* Q2 = (const float*)d_in[9];
    const float* Q3 = (const float*)d_in[10];

    int B = in_sizes[1] / 9;
    if (B > MAXB) B = MAXB;
    int N = in_sizes[0] / (3 * B);

    precompute_kernel<<<B, 256>>>(R, W1, b1, W2, b2, W3, b3, Q1, Q2, Q3);

    int pairs = N / 2;
    int gx = (pairs + THREADS * ITERS - 1) / (THREADS * ITERS);
    dim3 grid(gx, B);
    mf_main_kernel<<<grid, THREADS>>>(x, (float*)d_out, N, pairs);
}

// round 2
// speedup vs baseline: 1.2635x; 1.2635x over previous
#include <cuda_runtime.h>
#include <cuda_bf16.h>

// ---------------------------------------------------------------------------
// ParamMakeFeature: fold rotation into MLP weights, then run a packed-f32x2
// 3->15->15->15 MLP, 4 points per thread (2 f32x2 lanes sharing weight loads).
//
// Inputs (metadata order):
//  0: x      [B,3,N]   float32
//  1: randRm [B,3,3]   float32
//  2: W1 [15,3]  3: b1[15]  4: W2[15,15]  5: b2[15]  6: W3[15,15]  7: b3[15]
//  8: Q1 [3,3]   9: Q2[5,9]  10: Q3[7,27]
// Output: [B,15,N] float32
// ---------------------------------------------------------------------------

typedef unsigned long long u64;

#define FEAT 15
#define MAXB 32

// per-batch packed params (u64 = duplicated f32x2 pair), rows 16B-aligned:
//  [0,60):    stage1, 15 rows x 4:  [w0,w1,w2,b1]
//  [60,300):  stage2, 15 rows x 16: [w_0..w_14, b2]
//  [300,540): stage3, 15 rows x 16: [m_0..m_14, c3]
#define PAR_STRIDE 540

__device__ u64 g_params[MAXB * PAR_STRIDE];

__device__ __forceinline__ u64 pk2(float lo, float hi) {
    u64 r; asm("mov.b64 %0, {%1,%2};" : "=l"(r) : "f"(lo), "f"(hi)); return r;
}
__device__ __forceinline__ void upk2(u64 v, float& lo, float& hi) {
    asm("mov.b64 {%0,%1}, %2;" : "=f"(lo), "=f"(hi) : "l"(v));
}
__device__ __forceinline__ u64 ffma2(u64 a, u64 b, u64 c) {
    u64 d; asm("fma.rn.f32x2 %0, %1, %2, %3;" : "=l"(d) : "l"(a), "l"(b), "l"(c));
    return d;
}
__device__ __forceinline__ u64 relu2(u64 v) {
    float lo, hi; upk2(v, lo, hi);
    lo = fmaxf(lo, 0.f); hi = fmaxf(hi, 0.f);
    return pk2(lo, hi);
}

// ---------------------------------------------------------------------------
// Precompute kernel: one block per batch. Builds W1R = W1*R^T, D-blocks,
// M3 = Dblk*W3, c3 = Dblk*b3; writes duplicated f32x2 pairs in padded layout.
// ---------------------------------------------------------------------------
__global__ void precompute_kernel(
    const float* __restrict__ R_all,
    const float* __restrict__ W1, const float* __restrict__ b1,
    const float* __restrict__ W2, const float* __restrict__ b2,
    const float* __restrict__ W3, const float* __restrict__ b3,
    const float* __restrict__ Q1, const float* __restrict__ Q2,
    const float* __restrict__ Q3)
{
    const int b = blockIdx.x;
    const int tid = threadIdx.x;

    __shared__ float R[9];
    __shared__ float K2[81];
    __shared__ float K3[729];
    __shared__ float E2[9][5];
    __shared__ float E3[27][7];
    __shared__ float D1[3][3], D2[5][5], D3[7][7];
    __shared__ float M3[15][15], c3[15], W1Rs[15][3];

    if (tid < 9) R[tid] = R_all[b * 9 + tid];
    __syncthreads();

    if (tid < 81) {
        int row = tid / 9, col = tid % 9;
        int i = row / 3, k = row % 3, j = col / 3, l = col % 3;
        K2[tid] = R[i * 3 + j] * R[k * 3 + l];
    } else if (tid >= 96 && tid < 105) {
        int t = tid - 96, p = t / 3, q = t % 3;
        float s = 0.f;
        for (int i = 0; i < 3; i++)
            for (int j = 0; j < 3; j++)
                s += Q1[p * 3 + i] * R[i * 3 + j] * Q1[q * 3 + j];
        D1[p][q] = s;
    } else if (tid >= 112 && tid < 157) {
        int t = tid - 112, f = t / 3, j = t % 3;
        float s = 0.f;
        for (int i = 0; i < 3; i++) s += W1[f * 3 + i] * R[j * 3 + i];
        W1Rs[f][j] = s;
    }
    __syncthreads();

    if (tid < 45) {
        int i = tid / 5, q = tid % 5;
        float s = 0.f;
        for (int j = 0; j < 9; j++) s += K2[i * 9 + j] * Q2[q * 9 + j];
        E2[i][q] = s;
    }
    for (int idx = tid; idx < 729; idx += blockDim.x) {
        int row = idx / 27, col = idx % 27;
        int a = row / 3, m = row % 3, bb = col / 3, nn = col % 3;
        K3[idx] = K2[a * 9 + bb] * R[m * 3 + nn];
    }
    __syncthreads();

    if (tid < 25) {
        int p = tid / 5, q = tid % 5;
        float s = 0.f;
        for (int i = 0; i < 9; i++) s += Q2[p * 9 + i] * E2[i][q];
        D2[p][q] = s;
    } else if (tid >= 32 && tid < 32 + 189) {
        int t = tid - 32, u = t / 7, q = t % 7;
        float s = 0.f;
        for (int v = 0; v < 27; v++) s += K3[u * 27 + v] * Q3[q * 27 + v];
        E3[u][q] = s;
    }
    __syncthreads();

    if (tid < 49) {
        int p = tid / 7, q = tid % 7;
        float s = 0.f;
        for (int u = 0; u < 27; u++) s += Q3[p * 27 + u] * E3[u][q];
        D3[p][q] = s;
    }
    __syncthreads();

    if (tid < 225) {
        int p = tid / 15, f = tid % 15;
        float s = 0.f;
        if (p < 3)       { for (int q = 0; q < 3; q++) s += D1[p][q]     * W3[q * 15 + f]; }
        else if (p < 8)  { for (int q = 0; q < 5; q++) s += D2[p - 3][q] * W3[(3 + q) * 15 + f]; }
        else             { for (int q = 0; q < 7; q++) s += D3[p - 8][q] * W3[(8 + q) * 15 + f]; }
        M3[p][f] = s;
    } else if (tid < 240) {
        int p = tid - 225;
        float s = 0.f;
        if (p < 3)       { for (int q = 0; q < 3; q++) s += D1[p][q]     * b3[q]; }
        else if (p < 8)  { for (int q = 0; q < 5; q++) s += D2[p - 3][q] * b3[3 + q]; }
        else             { for (int q = 0; q < 7; q++) s += D3[p - 8][q] * b3[8 + q]; }
        c3[p] = s;
    }
    __syncthreads();

    // write duplicated-pair params, padded layout
    u64* dst = g_params + (size_t)b * PAR_STRIDE;
    for (int idx = tid; idx < PAR_STRIDE; idx += blockDim.x) {
        float v;
        if (idx < 60) {
            int f = idx >> 2, j = idx & 3;
            v = (j < 3) ? W1Rs[f][j] : b1[f];
        } else if (idx < 300) {
            int r = idx - 60, g = r >> 4, f = r & 15;
            v = (f < 15) ? W2[g * 15 + f] : b2[g];
        } else {
            int r = idx - 300, p = r >> 4, f = r & 15;
            v = (f < 15) ? M3[p][f] : c3[p];
        }
        dst[idx] = pk2(v, v);
    }
}

// ---------------------------------------------------------------------------
// Main kernel: each thread processes 4 adjacent points as 2 f32x2 lanes.
// Weights streamed from shared memory via LDS.128 (2 duplicated pairs/load),
// amortized over both lanes.
// ---------------------------------------------------------------------------
#define THREADS 256

__global__ __launch_bounds__(THREADS)
void mf_main_kernel(const float* __restrict__ x, float* __restrict__ out, int N)
{
    const int b = blockIdx.y;
    __shared__ __align__(16) u64 sw[PAR_STRIDE];
    {
        const u64* src = g_params + (size_t)b * PAR_STRIDE;
        for (int i = threadIdx.x; i < PAR_STRIDE; i += THREADS) sw[i] = src[i];
    }
    __syncthreads();

    const int t = blockIdx.x * THREADS + threadIdx.x;
    const int quads = N >> 2;

    const float* xb = x + (size_t)b * 3 * N;
    float* __restrict__ ob = out + (size_t)b * FEAT * N;

    if (t < quads) {
        float4 a0 = ((const float4*)(xb          ))[t];
        float4 a1 = ((const float4*)(xb + N      ))[t];
        float4 a2 = ((const float4*)(xb + 2 * (size_t)N))[t];
        u64 x0A = pk2(a0.x, a0.y), x0B = pk2(a0.z, a0.w);
        u64 x1A = pk2(a1.x, a1.y), x1B = pk2(a1.z, a1.w);
        u64 x2A = pk2(a2.x, a2.y), x2B = pk2(a2.z, a2.w);

        // stage 1: h1 = relu(W1R*x + b1)
        u64 h1A[FEAT], h1B[FEAT];
        {
            const ulonglong2* wrow = (const ulonglong2*)sw;
#pragma unroll
            for (int f = 0; f < FEAT; f++) {
                ulonglong2 w01 = wrow[f * 2 + 0];   // w0, w1
                ulonglong2 w2b = wrow[f * 2 + 1];   // w2, b1
                u64 aA = ffma2(x2A, w2b.x, w2b.y);
                u64 aB = ffma2(x2B, w2b.x, w2b.y);
                aA = ffma2(x1A, w01.y, aA);
                aB = ffma2(x1B, w01.y, aB);
                aA = ffma2(x0A, w01.x, aA);
                aB = ffma2(x0B, w01.x, aB);
                h1A[f] = relu2(aA);
                h1B[f] = relu2(aB);
            }
        }

        // stage 2: h2 = relu(W2*h1 + b2)
        u64 h2A[FEAT], h2B[FEAT];
#pragma unroll
        for (int g = 0; g < FEAT; g++) {
            const ulonglong2* row = (const ulonglong2*)(sw + 60 + g * 16);
            ulonglong2 t7 = row[7];                 // w14, b2
            u64 aA = ffma2(h1A[14], t7.x, t7.y);
            u64 aB = ffma2(h1B[14], t7.x, t7.y);
#pragma unroll
            for (int k = 0; k < 7; k++) {
                ulonglong2 w = row[k];
                aA = ffma2(h1A[2 * k], w.x, aA);
                aB = ffma2(h1B[2 * k], w.x, aB);
                aA = ffma2(h1A[2 * k + 1], w.y, aA);
                aB = ffma2(h1B[2 * k + 1], w.y, aB);
            }
            h2A[g] = relu2(aA);
            h2B[g] = relu2(aB);
        }

        // stage 3: y = M3*h2 + c3, store float4 per feature
#pragma unroll
        for (int pp = 0; pp < FEAT; pp++) {
            const ulonglong2* row = (const ulonglong2*)(sw + 300 + pp * 16);
            ulonglong2 t7 = row[7];                 // m14, c3
            u64 aA = ffma2(h2A[14], t7.x, t7.y);
            u64 aB = ffma2(h2B[14], t7.x, t7.y);
#pragma unroll
            for (int k = 0; k < 7; k++) {
                ulonglong2 w = row[k];
                aA = ffma2(h2A[2 * k], w.x, aA);
                aB = ffma2(h2B[2 * k], w.x, aB);
                aA = ffma2(h2A[2 * k + 1], w.y, aA);
                aB = ffma2(h2B[2 * k + 1], w.y, aB);
            }
            float4 st;
            upk2(aA, st.x, st.y);
            upk2(aB, st.z, st.w);
            ((float4*)(ob + (size_t)pp * N))[t] = st;
        }
    } else {
        // scalar tail for N % 4 leftover points
        const int rem = N & 3;
        const int tp = t - quads;
        if (tp < rem) {
            const int p = (quads << 2) + tp;
            const float* swf = (const float*)sw;   // lo half of duplicated pair
            float xv0 = xb[p], xv1 = xb[N + p], xv2 = xb[2 * (size_t)N + p];
            float h1[FEAT], h2[FEAT];
            for (int f = 0; f < FEAT; f++) {
                float a = swf[(f * 4 + 3) * 2];
                a += xv0 * swf[(f * 4 + 0) * 2];
                a += xv1 * swf[(f * 4 + 1) * 2];
                a += xv2 * swf[(f * 4 + 2) * 2];
                h1[f] = fmaxf(a, 0.f);
            }
            for (int g = 0; g < FEAT; g++) {
                float a = swf[(60 + g * 16 + 15) * 2];
                for (int f = 0; f < FEAT; f++)
                    a += h1[f] * swf[(60 + g * 16 + f) * 2];
                h2[g] = fmaxf(a, 0.f);
            }
            for (int pp = 0; pp < FEAT; pp++) {
                float a = swf[(300 + pp * 16 + 15) * 2];
                for (int f = 0; f < FEAT; f++)
                    a += h2[f] * swf[(300 + pp * 16 + f) * 2];
                ob[(size_t)pp * N + p] = a;
            }
        }
    }
}

// ---------------------------------------------------------------------------
extern "C" void kernel_launch(void* const* d_in, const int* in_sizes, int n_in,
                              void* d_out, int out_size)
{
    const float* x  = (const float*)d_in[0];
    const float* R  = (const float*)d_in[1];
    const float* W1 = (const float*)d_in[2];
    const float* b1 = (const float*)d_in[3];
    const float* W2 = (const float*)d_in[4];
    const float* b2 = (const float*)d_in[5];
    const float* W3 = (const float*)d_in[6];
    const float* b3 = (const float*)d_in[7];
    const float* Q1 = (const float*)d_in[8];
    const float* Q2 = (const float*)d_in[9];
    const float* Q3 = (const float*)d_in[10];

    int B = in_sizes[1] / 9;
    if (B > MAXB) B = MAXB;
    int N = in_sizes[0] / (3 * B);

    precompute_kernel<<<B, 256>>>(R, W1, b1, W2, b2, W3, b3, Q1, Q2, Q3);

    int quads = N >> 2;
    int gx = (quads + THREADS - 1) / THREADS;
    if (N & 3) gx += 1;   // guarantee spare threads for the scalar tail
    dim3 grid(gx, B);
    mf_main_kernel<<<grid, THREADS>>>(x, (float*)d_out, N);
}

// round 3
// speedup vs baseline: 1.8309x; 1.4491x over previous
#include <cuda_runtime.h>
#include <cuda_bf16.h>

// ---------------------------------------------------------------------------
// ParamMakeFeature: fold rotation into MLP weights, then run a packed-f32x2
// 3->15->15->15 MLP, 4 points per thread (2 f32x2 lanes sharing weight loads).
// 128-thread blocks so 3 blocks/SM fit in the register file (12 warps/SM).
// ---------------------------------------------------------------------------

typedef unsigned long long u64;

#define FEAT 15
#define MAXB 32

// per-batch packed params (u64 = duplicated f32x2 pair), rows 16B-aligned:
//  [0,60):    stage1, 15 rows x 4:  [w0,w1,w2,b1]
//  [60,300):  stage2, 15 rows x 16: [w_0..w_14, b2]
//  [300,540): stage3, 15 rows x 16: [m_0..m_14, c3]
#define PAR_STRIDE 540

__device__ u64 g_params[MAXB * PAR_STRIDE];

__device__ __forceinline__ u64 pk2(float lo, float hi) {
    u64 r; asm("mov.b64 %0, {%1,%2};" : "=l"(r) : "f"(lo), "f"(hi)); return r;
}
__device__ __forceinline__ void upk2(u64 v, float& lo, float& hi) {
    asm("mov.b64 {%0,%1}, %2;" : "=f"(lo), "=f"(hi) : "l"(v));
}
__device__ __forceinline__ u64 ffma2(u64 a, u64 b, u64 c) {
    u64 d; asm("fma.rn.f32x2 %0, %1, %2, %3;" : "=l"(d) : "l"(a), "l"(b), "l"(c));
    return d;
}
__device__ __forceinline__ u64 relu2(u64 v) {
    float lo, hi; upk2(v, lo, hi);
    lo = fmaxf(lo, 0.f); hi = fmaxf(hi, 0.f);
    return pk2(lo, hi);
}

// ---------------------------------------------------------------------------
// Precompute kernel: one block per batch. Builds W1R = W1*R^T, D-blocks,
// M3 = Dblk*W3, c3 = Dblk*b3; writes duplicated f32x2 pairs in padded layout.
// ---------------------------------------------------------------------------
__global__ void precompute_kernel(
    const float* __restrict__ R_all,
    const float* __restrict__ W1, const float* __restrict__ b1,
    const float* __restrict__ W2, const float* __restrict__ b2,
    const float* __restrict__ W3, const float* __restrict__ b3,
    const float* __restrict__ Q1, const float* __restrict__ Q2,
    const float* __restrict__ Q3)
{
    const int b = blockIdx.x;
    const int tid = threadIdx.x;

    __shared__ float R[9];
    __shared__ float K2[81];
    __shared__ float K3[729];
    __shared__ float E2[9][5];
    __shared__ float E3[27][7];
    __shared__ float D1[3][3], D2[5][5], D3[7][7];
    __shared__ float M3[15][15], c3[15], W1Rs[15][3];

    if (tid < 9) R[tid] = R_all[b * 9 + tid];
    __syncthreads();

    if (tid < 81) {
        int row = tid / 9, col = tid % 9;
        int i = row / 3, k = row % 3, j = col / 3, l = col % 3;
        K2[tid] = R[i * 3 + j] * R[k * 3 + l];
    } else if (tid >= 96 && tid < 105) {
        int t = tid - 96, p = t / 3, q = t % 3;
        float s = 0.f;
        for (int i = 0; i < 3; i++)
            for (int j = 0; j < 3; j++)
                s += Q1[p * 3 + i] * R[i * 3 + j] * Q1[q * 3 + j];
        D1[p][q] = s;
    } else if (tid >= 112 && tid < 157) {
        int t = tid - 112, f = t / 3, j = t % 3;
        float s = 0.f;
        for (int i = 0; i < 3; i++) s += W1[f * 3 + i] * R[j * 3 + i];
        W1Rs[f][j] = s;
    }
    __syncthreads();

    if (tid < 45) {
        int i = tid / 5, q = tid % 5;
        float s = 0.f;
        for (int j = 0; j < 9; j++) s += K2[i * 9 + j] * Q2[q * 9 + j];
        E2[i][q] = s;
    }
    for (int idx = tid; idx < 729; idx += blockDim.x) {
        int row = idx / 27, col = idx % 27;
        int a = row / 3, m = row % 3, bb = col / 3, nn = col % 3;
        K3[idx] = K2[a * 9 + bb] * R[m * 3 + nn];
    }
    __syncthreads();

    if (tid < 25) {
        int p = tid / 5, q = tid % 5;
        float s = 0.f;
        for (int i = 0; i < 9; i++) s += Q2[p * 9 + i] * E2[i][q];
        D2[p][q] = s;
    } else if (tid >= 32 && tid < 32 + 189) {
        int t = tid - 32, u = t / 7, q = t % 7;
        float s = 0.f;
        for (int v = 0; v < 27; v++) s += K3[u * 27 + v] * Q3[q * 27 + v];
        E3[u][q] = s;
    }
    __syncthreads();

    if (tid < 49) {
        int p = tid / 7, q = tid % 7;
        float s = 0.f;
        for (int u = 0; u < 27; u++) s += Q3[p * 27 + u] * E3[u][q];
        D3[p][q] = s;
    }
    __syncthreads();

    if (tid < 225) {
        int p = tid / 15, f = tid % 15;
        float s = 0.f;
        if (p < 3)       { for (int q = 0; q < 3; q++) s += D1[p][q]     * W3[q * 15 + f]; }
        else if (p < 8)  { for (int q = 0; q < 5; q++) s += D2[p - 3][q] * W3[(3 + q) * 15 + f]; }
        else             { for (int q = 0; q < 7; q++) s += D3[p - 8][q] * W3[(8 + q) * 15 + f]; }
        M3[p][f] = s;
    } else if (tid < 240) {
        int p = tid - 225;
        float s = 0.f;
        if (p < 3)       { for (int q = 0; q < 3; q++) s += D1[p][q]     * b3[q]; }
        else if (p < 8)  { for (int q = 0; q < 5; q++) s += D2[p - 3][q] * b3[3 + q]; }
        else             { for (int q = 0; q < 7; q++) s += D3[p - 8][q] * b3[8 + q]; }
        c3[p] = s;
    }
    __syncthreads();

    // write duplicated-pair params, padded layout
    u64* dst = g_params + (size_t)b * PAR_STRIDE;
    for (int idx = tid; idx < PAR_STRIDE; idx += blockDim.x) {
        float v;
        if (idx < 60) {
            int f = idx >> 2, j = idx & 3;
            v = (j < 3) ? W1Rs[f][j] : b1[f];
        } else if (idx < 300) {
            int r = idx - 60, g = r >> 4, f = r & 15;
            v = (f < 15) ? W2[g * 15 + f] : b2[g];
        } else {
            int r = idx - 300, p = r >> 4, f = r & 15;
            v = (f < 15) ? M3[p][f] : c3[p];
        }
        dst[idx] = pk2(v, v);
    }
}

// ---------------------------------------------------------------------------
// Main kernel: each thread processes 4 adjacent points as 2 f32x2 lanes.
// Weights streamed from shared memory via LDS.128 (2 duplicated pairs/load),
// amortized over both lanes. 128-thread blocks -> 3 blocks/SM in the RF.
// ---------------------------------------------------------------------------
#define THREADS 128

__global__ __launch_bounds__(THREADS)
void mf_main_kernel(const float* __restrict__ x, float* __restrict__ out, int N)
{
    const int b = blockIdx.y;
    __shared__ __align__(16) u64 sw[PAR_STRIDE];
    {
        const u64* src = g_params + (size_t)b * PAR_STRIDE;
        for (int i = threadIdx.x; i < PAR_STRIDE; i += THREADS) sw[i] = src[i];
    }
    __syncthreads();

    const int t = blockIdx.x * THREADS + threadIdx.x;
    const int quads = N >> 2;

    const float* xb = x + (size_t)b * 3 * N;
    float* __restrict__ ob = out + (size_t)b * FEAT * N;

    if (t < quads) {
        float4 a0 = __ldcs((const float4*)(xb                 ) + t);
        float4 a1 = __ldcs((const float4*)(xb + N             ) + t);
        float4 a2 = __ldcs((const float4*)(xb + 2 * (size_t)N ) + t);
        u64 x0A = pk2(a0.x, a0.y), x0B = pk2(a0.z, a0.w);
        u64 x1A = pk2(a1.x, a1.y), x1B = pk2(a1.z, a1.w);
        u64 x2A = pk2(a2.x, a2.y), x2B = pk2(a2.z, a2.w);

        // stage 1: h1 = relu(W1R*x + b1)
        u64 h1A[FEAT], h1B[FEAT];
        {
            const ulonglong2* wrow = (const ulonglong2*)sw;
#pragma unroll
            for (int f = 0; f < FEAT; f++) {
                ulonglong2 w01 = wrow[f * 2 + 0];   // w0, w1
                ulonglong2 w2b = wrow[f * 2 + 1];   // w2, b1
                u64 aA = ffma2(x2A, w2b.x, w2b.y);
                u64 aB = ffma2(x2B, w2b.x, w2b.y);
                aA = ffma2(x1A, w01.y, aA);
                aB = ffma2(x1B, w01.y, aB);
                aA = ffma2(x0A, w01.x, aA);
                aB = ffma2(x0B, w01.x, aB);
                h1A[f] = relu2(aA);
                h1B[f] = relu2(aB);
            }
        }

        // stage 2: h2 = relu(W2*h1 + b2)
        u64 h2A[FEAT], h2B[FEAT];
#pragma unroll
        for (int g = 0; g < FEAT; g++) {
            const ulonglong2* row = (const ulonglong2*)(sw + 60 + g * 16);
            ulonglong2 t7 = row[7];                 // w14, b2
            u64 aA = ffma2(h1A[14], t7.x, t7.y);
            u64 aB = ffma2(h1B[14], t7.x, t7.y);
#pragma unroll
            for (int k = 0; k < 7; k++) {
                ulonglong2 w = row[k];
                aA = ffma2(h1A[2 * k], w.x, aA);
                aB = ffma2(h1B[2 * k], w.x, aB);
                aA = ffma2(h1A[2 * k + 1], w.y, aA);
                aB = ffma2(h1B[2 * k + 1], w.y, aB);
            }
            h2A[g] = relu2(aA);
            h2B[g] = relu2(aB);
        }

        // stage 3: y = M3*h2 + c3, store float4 per feature (streaming)
#pragma unroll
        for (int pp = 0; pp < FEAT; pp++) {
            const ulonglong2* row = (const ulonglong2*)(sw + 300 + pp * 16);
            ulonglong2 t7 = row[7];                 // m14, c3
            u64 aA = ffma2(h2A[14], t7.x, t7.y);
            u64 aB = ffma2(h2B[14], t7.x, t7.y);
#pragma unroll
            for (int k = 0; k < 7; k++) {
                ulonglong2 w = row[k];
                aA = ffma2(h2A[2 * k], w.x, aA);
                aB = ffma2(h2B[2 * k], w.x, aB);
                aA = ffma2(h2A[2 * k + 1], w.y, aA);
                aB = ffma2(h2B[2 * k + 1], w.y, aB);
            }
            float4 st;
            upk2(aA, st.x, st.y);
            upk2(aB, st.z, st.w);
            __stcs((float4*)(ob + (size_t)pp * N) + t, st);
        }
    } else {
        // scalar tail for N % 4 leftover points
        const int rem = N & 3;
        const int tp = t - quads;
        if (tp < rem) {
            const int p = (quads << 2) + tp;
            const float* swf = (const float*)sw;   // lo half of duplicated pair
            float xv0 = xb[p], xv1 = xb[N + p], xv2 = xb[2 * (size_t)N + p];
            float h1[FEAT], h2[FEAT];
            for (int f = 0; f < FEAT; f++) {
                float a = swf[(f * 4 + 3) * 2];
                a += xv0 * swf[(f * 4 + 0) * 2];
                a += xv1 * swf[(f * 4 + 1) * 2];
                a += xv2 * swf[(f * 4 + 2) * 2];
                h1[f] = fmaxf(a, 0.f);
            }
            for (int g = 0; g < FEAT; g++) {
                float a = swf[(60 + g * 16 + 15) * 2];
                for (int f = 0; f < FEAT; f++)
                    a += h1[f] * swf[(60 + g * 16 + f) * 2];
                h2[g] = fmaxf(a, 0.f);
            }
            for (int pp = 0; pp < FEAT; pp++) {
                float a = swf[(300 + pp * 16 + 15) * 2];
                for (int f = 0; f < FEAT; f++)
                    a += h2[f] * swf[(300 + pp * 16 + f) * 2];
                ob[(size_t)pp * N + p] = a;
            }
        }
    }
}

// ---------------------------------------------------------------------------
extern "C" void kernel_launch(void* const* d_in, const int* in_sizes, int n_in,
                              void* d_out, int out_size)
{
    const float* x  = (const float*)d_in[0];
    const float* R  = (const float*)d_in[1];
    const float* W1 = (const float*)d_in[2];
    const float* b1 = (const float*)d_in[3];
    const float* W2 = (const float*)d_in[4];
    const float* b2 = (const float*)d_in[5];
    const float* W3 = (const float*)d_in[6];
    const float* b3 = (const float*)d_in[7];
    const float* Q1 = (const float*)d_in[8];
    const float* Q2 = (const float*)d_in[9];
    const float* Q3 = (const float*)d_in[10];

    int B = in_sizes[1] / 9;
    if (B > MAXB) B = MAXB;
    int N = in_sizes[0] / (3 * B);

    precompute_kernel<<<B, 256>>>(R, W1, b1, W2, b2, W3, b3, Q1, Q2, Q3);

    int quads = N >> 2;
    int gx = (quads + THREADS - 1) / THREADS;
    if (N & 3) gx += 1;   // guarantee spare threads for the scalar tail
    dim3 grid(gx, B);
    mf_main_kernel<<<grid, THREADS>>>(x, (float*)d_out, N);
}